// round 3
// baseline (speedup 1.0000x reference)
#include <cuda_runtime.h>
#include <cuda_bf16.h>
#include <cstdint>
#include <cstddef>

#define DEV __device__ __forceinline__

// ---------------- problem constants ----------------
constexpr int BATCH  = 16384;
constexpr int HDIM   = 1024;
constexpr int INDIM  = 512;
constexpr int OUTDIM = 512;
constexpr int NBLK   = 2;
constexpr float BN_EPS = 1e-3f;

// ---------------- GEMM tiling ----------------
constexpr int BM   = 128;
constexpr int BNT  = 128;
constexpr int BK   = 32;
constexpr int LDA  = BK  + 8;   // bf16 elems per A smem row (pad -> conflict-free ldmatrix)
constexpr int LDB  = BNT + 8;   // bf16 elems per B smem row
constexpr int NTH  = 256;       // 8 warps: 4 (m) x 2 (n); warp tile 32x64

// ---------------- persistent device scratch (no allocations allowed) ----------------
__device__ float g_y [BATCH * HDIM];
__device__ float g_h [BATCH * HDIM];
__device__ float g_k [4][BATCH * HDIM];
__device__ float g_inv[NBLK * 2 * HDIM];

// ---------------- small helpers ----------------
DEV uint32_t sptr(const void* p) { return (uint32_t)__cvta_generic_to_shared(p); }

DEV void ldm4(uint32_t r[4], uint32_t a) {
    asm volatile("ldmatrix.sync.aligned.m8n8.x4.shared.b16 {%0,%1,%2,%3}, [%4];"
                 : "=r"(r[0]), "=r"(r[1]), "=r"(r[2]), "=r"(r[3]) : "r"(a));
}
DEV void ldm4t(uint32_t r[4], uint32_t a) {
    asm volatile("ldmatrix.sync.aligned.m8n8.x4.trans.shared.b16 {%0,%1,%2,%3}, [%4];"
                 : "=r"(r[0]), "=r"(r[1]), "=r"(r[2]), "=r"(r[3]) : "r"(a));
}
DEV void mma16816(float d[4], const uint32_t a[4], const uint32_t b[2]) {
    asm volatile("mma.sync.aligned.m16n8k16.row.col.f32.bf16.bf16.f32 "
                 "{%0,%1,%2,%3}, {%4,%5,%6,%7}, {%8,%9}, {%0,%1,%2,%3};"
                 : "+f"(d[0]), "+f"(d[1]), "+f"(d[2]), "+f"(d[3])
                 : "r"(a[0]), "r"(a[1]), "r"(a[2]), "r"(a[3]), "r"(b[0]), "r"(b[1]));
}
DEV uint32_t packbf(float a, float b) {
    __nv_bfloat162 t = __floats2bfloat162_rn(a, b);
    return *reinterpret_cast<uint32_t*>(&t);
}
DEV float bf16_round(float v) { return __bfloat162float(__float2bfloat16_rn(v)); }

// ---------------- modes ----------------
// MODE 0: split-precision GEMM (hi/lo bf16, 3 mma passes) + bias        (prologue / epilogue)
// MODE 1: A-load = relu(bn0(y + cc*k)); epilogue = relu(bn1(acc + b1))  (ODE GEMM #1)
// MODE 2: plain bf16 A; epilogue = acc + b2                             (ODE GEMM #2)
template <int MODE>
__global__ void __launch_bounds__(NTH)
gemm_k(const float* __restrict__ A, const float* __restrict__ A2, float cc,
       const float* __restrict__ W,
       const float* __restrict__ bias,
       const float* __restrict__ mean0, const float* __restrict__ inv0, const float* __restrict__ beta0,
       const float* __restrict__ mean1, const float* __restrict__ inv1, const float* __restrict__ beta1,
       float* __restrict__ C, int M, int K, int N)
{
    constexpr bool SPLIT = (MODE == 0);
    __shared__ __align__(16) __nv_bfloat16 AsH[BM * LDA];
    __shared__ __align__(16) __nv_bfloat16 BsH[BK * LDB];
    __shared__ __align__(16) __nv_bfloat16 AsL[SPLIT ? BM * LDA : 8];
    __shared__ __align__(16) __nv_bfloat16 BsL[SPLIT ? BK * LDB : 8];

    const int tid  = threadIdx.x;
    const int lane = tid & 31;
    const int warp = tid >> 5;
    const int wm   = warp >> 1;        // 0..3
    const int wn   = warp & 1;         // 0..1
    const int m0   = blockIdx.y * BM;
    const int n0   = blockIdx.x * BNT;

    float acc[2][8][4];
#pragma unroll
    for (int i = 0; i < 2; i++)
#pragma unroll
        for (int j = 0; j < 8; j++)
#pragma unroll
            for (int q = 0; q < 4; q++) acc[i][j][q] = 0.f;

    const int arow = tid >> 3;              // A: 32 rows per pass, 8 float4/row
    const int akq  = (tid & 7) << 2;        // k offset (4 floats)
    const int brow = tid >> 5;              // B: 8 rows per pass, 32 float4/row
    const int bnq  = (tid & 31) << 2;       // n offset (4 floats)

    for (int k0 = 0; k0 < K; k0 += BK) {
        // ---- global -> regs (overlaps previous tile's compute) ----
        float av[4][4];
        float mnv[4], ivv[4], btv[4];
        if constexpr (MODE == 1) {
            const float4 mn = *reinterpret_cast<const float4*>(mean0 + k0 + akq);
            const float4 iv = *reinterpret_cast<const float4*>(inv0  + k0 + akq);
            const float4 bt = *reinterpret_cast<const float4*>(beta0 + k0 + akq);
            mnv[0]=mn.x; mnv[1]=mn.y; mnv[2]=mn.z; mnv[3]=mn.w;
            ivv[0]=iv.x; ivv[1]=iv.y; ivv[2]=iv.z; ivv[3]=iv.w;
            btv[0]=bt.x; btv[1]=bt.y; btv[2]=bt.z; btv[3]=bt.w;
        }
#pragma unroll
        for (int p = 0; p < 4; p++) {
            const int r = arow + p * 32;
            const float4 x4 = *reinterpret_cast<const float4*>(A + (size_t)(m0 + r) * K + k0 + akq);
            av[p][0] = x4.x; av[p][1] = x4.y; av[p][2] = x4.z; av[p][3] = x4.w;
            if constexpr (MODE == 1) {
                const float4 q4 = *reinterpret_cast<const float4*>(A2 + (size_t)(m0 + r) * K + k0 + akq);
                const float qv[4] = {q4.x, q4.y, q4.z, q4.w};
#pragma unroll
                for (int j = 0; j < 4; j++) {
                    float ys = av[p][j] + cc * qv[j];
                    av[p][j] = fmaxf((ys - mnv[j]) * ivv[j] + btv[j], 0.f);
                }
            }
        }
        float bv[4][4];
#pragma unroll
        for (int p = 0; p < 4; p++) {
            const int r = brow + p * 8;
            const float4 w4 = *reinterpret_cast<const float4*>(W + (size_t)(k0 + r) * N + n0 + bnq);
            bv[p][0] = w4.x; bv[p][1] = w4.y; bv[p][2] = w4.z; bv[p][3] = w4.w;
        }

        __syncthreads();   // previous tile's compute done before overwriting smem

        // ---- regs -> smem (convert / split) ----
#pragma unroll
        for (int p = 0; p < 4; p++) {
            const int r = arow + p * 32;
            if constexpr (!SPLIT) {
                uint2 u;
                u.x = packbf(av[p][0], av[p][1]);
                u.y = packbf(av[p][2], av[p][3]);
                *reinterpret_cast<uint2*>(&AsH[r * LDA + akq]) = u;
            } else {
                float h0 = bf16_round(av[p][0]), h1 = bf16_round(av[p][1]);
                float h2 = bf16_round(av[p][2]), h3 = bf16_round(av[p][3]);
                uint2 uh, ul;
                uh.x = packbf(h0, h1); uh.y = packbf(h2, h3);
                ul.x = packbf(av[p][0] - h0, av[p][1] - h1);
                ul.y = packbf(av[p][2] - h2, av[p][3] - h3);
                *reinterpret_cast<uint2*>(&AsH[r * LDA + akq]) = uh;
                *reinterpret_cast<uint2*>(&AsL[r * LDA + akq]) = ul;
            }
        }
#pragma unroll
        for (int p = 0; p < 4; p++) {
            const int r = brow + p * 8;
            if constexpr (!SPLIT) {
                uint2 u;
                u.x = packbf(bv[p][0], bv[p][1]);
                u.y = packbf(bv[p][2], bv[p][3]);
                *reinterpret_cast<uint2*>(&BsH[r * LDB + bnq]) = u;
            } else {
                float h0 = bf16_round(bv[p][0]), h1 = bf16_round(bv[p][1]);
                float h2 = bf16_round(bv[p][2]), h3 = bf16_round(bv[p][3]);
                uint2 uh, ul;
                uh.x = packbf(h0, h1); uh.y = packbf(h2, h3);
                ul.x = packbf(bv[p][0] - h0, bv[p][1] - h1);
                ul.y = packbf(bv[p][2] - h2, bv[p][3] - h3);
                *reinterpret_cast<uint2*>(&BsH[r * LDB + bnq]) = uh;
                *reinterpret_cast<uint2*>(&BsL[r * LDB + bnq]) = ul;
            }
        }

        __syncthreads();

        // ---- tensor-core compute on the tile ----
#pragma unroll
        for (int ks = 0; ks < BK; ks += 16) {
            uint32_t aH[2][4], bH[8][2];
            uint32_t aL[SPLIT ? 2 : 1][4], bL[SPLIT ? 8 : 1][2];
#pragma unroll
            for (int mt = 0; mt < 2; mt++) {
                const int r = wm * 32 + mt * 16 + (lane & 15);
                const int c = ks + ((lane >> 4) << 3);
                ldm4(aH[mt], sptr(&AsH[r * LDA + c]));
                if constexpr (SPLIT) ldm4(aL[mt], sptr(&AsL[r * LDA + c]));
            }
#pragma unroll
            for (int np = 0; np < 4; np++) {
                const int r = ks + (((lane >> 3) & 1) << 3) + (lane & 7);
                const int c = wn * 64 + np * 16 + ((lane >> 4) << 3);
                uint32_t t[4];
                ldm4t(t, sptr(&BsH[r * LDB + c]));
                bH[np * 2][0] = t[0]; bH[np * 2][1] = t[1];
                bH[np * 2 + 1][0] = t[2]; bH[np * 2 + 1][1] = t[3];
                if constexpr (SPLIT) {
                    ldm4t(t, sptr(&BsL[r * LDB + c]));
                    bL[np * 2][0] = t[0]; bL[np * 2][1] = t[1];
                    bL[np * 2 + 1][0] = t[2]; bL[np * 2 + 1][1] = t[3];
                }
            }
#pragma unroll
            for (int mt = 0; mt < 2; mt++)
#pragma unroll
                for (int nt = 0; nt < 8; nt++) {
                    mma16816(acc[mt][nt], aH[mt], bH[nt]);
                    if constexpr (SPLIT) {
                        mma16816(acc[mt][nt], aH[mt], bL[nt]);
                        mma16816(acc[mt][nt], aL[mt], bH[nt]);
                    }
                }
        }
        __syncthreads();
    }

    // ---- epilogue ----
#pragma unroll
    for (int mt = 0; mt < 2; mt++) {
        const int row = m0 + wm * 32 + mt * 16 + (lane >> 2);
#pragma unroll
        for (int nt = 0; nt < 8; nt++) {
            const int col = n0 + wn * 64 + nt * 8 + ((lane & 3) << 1);
            const float2 bs = *reinterpret_cast<const float2*>(bias + col);
            float v0 = acc[mt][nt][0] + bs.x;
            float v1 = acc[mt][nt][1] + bs.y;
            float v2 = acc[mt][nt][2] + bs.x;
            float v3 = acc[mt][nt][3] + bs.y;
            if constexpr (MODE == 1) {
                const float2 mn = *reinterpret_cast<const float2*>(mean1 + col);
                const float2 iv = *reinterpret_cast<const float2*>(inv1  + col);
                const float2 bt = *reinterpret_cast<const float2*>(beta1 + col);
                v0 = fmaxf((v0 - mn.x) * iv.x + bt.x, 0.f);
                v1 = fmaxf((v1 - mn.y) * iv.y + bt.y, 0.f);
                v2 = fmaxf((v2 - mn.x) * iv.x + bt.x, 0.f);
                v3 = fmaxf((v3 - mn.y) * iv.y + bt.y, 0.f);
            }
            *reinterpret_cast<float2*>(C + (size_t)row * N + col)       = make_float2(v0, v1);
            *reinterpret_cast<float2*>(C + (size_t)(row + 8) * N + col) = make_float2(v2, v3);
        }
    }
}

// inv = gamma * rsqrt(var + eps)
__global__ void prep_inv(const float* __restrict__ gamma, const float* __restrict__ var,
                         float* __restrict__ inv, int n)
{
    int i = blockIdx.x * blockDim.x + threadIdx.x;
    if (i < n) inv[i] = gamma[i] * rsqrtf(var[i] + BN_EPS);
}

// y += s*(k1 + 2 k2 + 2 k3 + k4); optional relu (end of each ODE block)
__global__ void rk4_update(float* __restrict__ y,
                           const float* __restrict__ k1, const float* __restrict__ k2,
                           const float* __restrict__ k3, const float* __restrict__ k4,
                           float s, int do_relu, int n4)
{
    int i = blockIdx.x * blockDim.x + threadIdx.x;
    if (i >= n4) return;
    float4 yv = reinterpret_cast<float4*>(y)[i];
    float4 a = reinterpret_cast<const float4*>(k1)[i];
    float4 b = reinterpret_cast<const float4*>(k2)[i];
    float4 c = reinterpret_cast<const float4*>(k3)[i];
    float4 d = reinterpret_cast<const float4*>(k4)[i];
    yv.x += s * (a.x + 2.f * (b.x + c.x) + d.x);
    yv.y += s * (a.y + 2.f * (b.y + c.y) + d.y);
    yv.z += s * (a.z + 2.f * (b.z + c.z) + d.z);
    yv.w += s * (a.w + 2.f * (b.w + c.w) + d.w);
    if (do_relu) {
        yv.x = fmaxf(yv.x, 0.f); yv.y = fmaxf(yv.y, 0.f);
        yv.z = fmaxf(yv.z, 0.f); yv.w = fmaxf(yv.w, 0.f);
    }
    reinterpret_cast<float4*>(y)[i] = yv;
}

extern "C" void kernel_launch(void* const* d_in, const int* in_sizes, int n_in,
                              void* d_out, int out_size)
{
    const float* X        = (const float*)d_in[0];
    const float* W_in     = (const float*)d_in[1];
    const float* b_in     = (const float*)d_in[2];
    const float* bn_gamma = (const float*)d_in[3];
    const float* bn_beta  = (const float*)d_in[4];
    const float* bn_mean  = (const float*)d_in[5];
    const float* bn_var   = (const float*)d_in[6];
    const float* W1       = (const float*)d_in[7];
    const float* b1       = (const float*)d_in[8];
    const float* W2       = (const float*)d_in[9];
    const float* b2       = (const float*)d_in[10];
    const float* W_out    = (const float*)d_in[11];
    const float* b_out    = (const float*)d_in[12];

    float *y, *hbuf, *kbase, *inv;
    cudaGetSymbolAddress((void**)&y,     g_y);
    cudaGetSymbolAddress((void**)&hbuf,  g_h);
    cudaGetSymbolAddress((void**)&kbase, g_k);
    cudaGetSymbolAddress((void**)&inv,   g_inv);
    float* kb[4];
    for (int i = 0; i < 4; i++) kb[i] = kbase + (size_t)i * BATCH * HDIM;

    prep_inv<<<(NBLK * 2 * HDIM + 255) / 256, 256>>>(bn_gamma, bn_var, inv, NBLK * 2 * HDIM);

    const dim3 blk(NTH);
    const dim3 grid_h(HDIM / BNT, BATCH / BM);    // (8, 128)
    const dim3 grid_o(OUTDIM / BNT, BATCH / BM);  // (4, 128)

    // prologue: y = X @ W_in + b_in   (split precision)
    gemm_k<0><<<grid_h, blk>>>(X, X, 0.f, W_in, b_in,
                               nullptr, nullptr, nullptr, nullptr, nullptr, nullptr,
                               y, BATCH, INDIM, HDIM);

    const float hstep = 0.5f;                 // 2 RK4 steps per block over [0,1]
    for (int b = 0; b < NBLK; ++b) {
        const float* W1b = W1 + (size_t)b * HDIM * HDIM;
        const float* W2b = W2 + (size_t)b * HDIM * HDIM;
        const float* b1b = b1 + b * HDIM;
        const float* b2b = b2 + b * HDIM;
        const float* mn0 = bn_mean + (size_t)(b * 2 + 0) * HDIM;
        const float* mn1 = bn_mean + (size_t)(b * 2 + 1) * HDIM;
        const float* bt0 = bn_beta + (size_t)(b * 2 + 0) * HDIM;
        const float* bt1 = bn_beta + (size_t)(b * 2 + 1) * HDIM;
        const float* iv0 = inv + (b * 2 + 0) * HDIM;
        const float* iv1 = inv + (b * 2 + 1) * HDIM;

        for (int s = 0; s < 2; ++s) {
            const float cs[4]  = {0.f, 0.5f * hstep, 0.5f * hstep, hstep};
            const float* kin[4] = {y, kb[0], kb[1], kb[2]};   // stage inputs: y + cs*kin
            for (int st = 0; st < 4; ++st) {
                gemm_k<1><<<grid_h, blk>>>(y, kin[st], cs[st], W1b, b1b,
                                           mn0, iv0, bt0, mn1, iv1, bt1,
                                           hbuf, BATCH, HDIM, HDIM);
                gemm_k<2><<<grid_h, blk>>>(hbuf, nullptr, 0.f, W2b, b2b,
                                           nullptr, nullptr, nullptr, nullptr, nullptr, nullptr,
                                           kb[st], BATCH, HDIM, HDIM);
            }
            const int n4 = BATCH * HDIM / 4;
            rk4_update<<<(n4 + 255) / 256, 256>>>(y, kb[0], kb[1], kb[2], kb[3],
                                                  hstep / 6.f, (s == 1) ? 1 : 0, n4);
        }
    }

    // epilogue: out = y @ W_out + b_out   (split precision; y already relu'd)
    gemm_k<0><<<grid_o, blk>>>(y, y, 0.f, W_out, b_out,
                               nullptr, nullptr, nullptr, nullptr, nullptr, nullptr,
                               (float*)d_out, BATCH, HDIM, OUTDIM);
}

// round 4
// speedup vs baseline: 2.0522x; 2.0522x over previous
#include <cuda_runtime.h>
#include <cuda_bf16.h>
#include <cstdint>
#include <cstddef>

#define DEV __device__ __forceinline__
using bf16 = __nv_bfloat16;

// ---------------- problem constants ----------------
constexpr int BATCH  = 16384;
constexpr int HDIM   = 1024;
constexpr int INDIM  = 512;
constexpr int OUTDIM = 512;
constexpr int NBLK   = 2;
constexpr float BN_EPS = 1e-3f;

// ---------------- GEMM tiling ----------------
constexpr int BM  = 128;
constexpr int BNT = 128;
constexpr int BK  = 64;
constexpr int NTH = 256;          // 8 warps: 4 (m) x 2 (n); warp tile 32x64
constexpr int LDA = BK + 8;       // 72  -> 144B rows, 16B-aligned, conflict-free ldmatrix
constexpr int LDB = BNT + 8;      // 136 -> 272B rows
constexpr int A_ELE = BM * LDA;   // per-stage A elems
constexpr int B_ELE = BK * LDB;   // per-stage B elems
constexpr int PLAIN_SMEM = 3 * (A_ELE + B_ELE) * 2;       // 107,520 B (3 stages)
constexpr int SPLIT_SMEM = 2 * 2 * (A_ELE + B_ELE) * 2;   // 143,360 B (2 stages, hi+lo)

// ---------------- persistent device scratch (no allocations allowed) ----------------
__device__ float g_y [BATCH * HDIM];
__device__ bf16  g_a [BATCH * HDIM];
__device__ bf16  g_h [BATCH * HDIM];
__device__ bf16  g_k [4][BATCH * HDIM];
__device__ bf16  g_yh[BATCH * HDIM];
__device__ bf16  g_yl[BATCH * HDIM];
__device__ bf16  g_xh[BATCH * INDIM];
__device__ bf16  g_xl[BATCH * INDIM];
__device__ bf16  g_w1[NBLK * HDIM * HDIM];
__device__ bf16  g_w2[NBLK * HDIM * HDIM];
__device__ bf16  g_wih[INDIM * HDIM];
__device__ bf16  g_wil[INDIM * HDIM];
__device__ bf16  g_woh[HDIM * OUTDIM];
__device__ bf16  g_wol[HDIM * OUTDIM];
__device__ float g_inv[NBLK * 2 * HDIM];

// ---------------- small helpers ----------------
DEV uint32_t sptr(const void* p) { return (uint32_t)__cvta_generic_to_shared(p); }

DEV void ldm4(uint32_t r[4], uint32_t a) {
    asm volatile("ldmatrix.sync.aligned.m8n8.x4.shared.b16 {%0,%1,%2,%3}, [%4];"
                 : "=r"(r[0]), "=r"(r[1]), "=r"(r[2]), "=r"(r[3]) : "r"(a));
}
DEV void ldm4t(uint32_t r[4], uint32_t a) {
    asm volatile("ldmatrix.sync.aligned.m8n8.x4.trans.shared.b16 {%0,%1,%2,%3}, [%4];"
                 : "=r"(r[0]), "=r"(r[1]), "=r"(r[2]), "=r"(r[3]) : "r"(a));
}
DEV void mma16816(float d[4], const uint32_t a[4], const uint32_t b[2]) {
    asm volatile("mma.sync.aligned.m16n8k16.row.col.f32.bf16.bf16.f32 "
                 "{%0,%1,%2,%3}, {%4,%5,%6,%7}, {%8,%9}, {%0,%1,%2,%3};"
                 : "+f"(d[0]), "+f"(d[1]), "+f"(d[2]), "+f"(d[3])
                 : "r"(a[0]), "r"(a[1]), "r"(a[2]), "r"(a[3]), "r"(b[0]), "r"(b[1]));
}
DEV uint32_t packbf(float a, float b) {
    __nv_bfloat162 t = __floats2bfloat162_rn(a, b);
    return *reinterpret_cast<uint32_t*>(&t);
}
DEV float bf16_round(float v) { return __bfloat162float(__float2bfloat16_rn(v)); }

DEV void cpa(uint32_t dst, const void* src) {
    asm volatile("cp.async.cg.shared.global [%0], [%1], 16;\n" :: "r"(dst), "l"(src));
}
DEV void cpc() { asm volatile("cp.async.commit_group;\n"); }
template <int N> DEV void cpw() { asm volatile("cp.async.wait_group %0;\n" :: "n"(N)); }

// ---------------- unified pipelined bf16 GEMM ----------------
// MODE 0 (SPLIT): acc = Ah·Bh + Ah·Bl + Al·Bh; v = acc + bias;
//                 Cf = v (fp32); if Ab: Ab = relu(bn(v))           [prologue/epilogue]
// MODE 1: v = acc + bias; Cb = relu(bn(v))  bf16                   [ODE GEMM #1 -> h]
// MODE 2: v = acc + bias; Cb = v bf16 (stage k);
//         if Ab: Ab = relu(bn(yin + cnext*v)) bf16                 [ODE GEMM #2 -> k, a_next]
template <int MODE, int STAGES>
__global__ void __launch_bounds__(NTH, (MODE == 0) ? 1 : 2)
gemm_bf16(const bf16* __restrict__ Ah, const bf16* __restrict__ Al,
          const bf16* __restrict__ Bh, const bf16* __restrict__ Bl,
          const float* __restrict__ bias,
          const float* __restrict__ mn, const float* __restrict__ iv, const float* __restrict__ bt,
          const float* __restrict__ yin, float cnext,
          float* __restrict__ Cf, bf16* __restrict__ Cb, bf16* __restrict__ Ab,
          int M, int K, int N)
{
    constexpr bool SPLIT = (MODE == 0);
    constexpr int SSET = (A_ELE + B_ELE) * (SPLIT ? 2 : 1);   // smem elems per stage
    extern __shared__ __align__(16) bf16 smem[];

    const int tid = threadIdx.x, lane = tid & 31, warp = tid >> 5;
    const int wm = warp >> 1, wn = warp & 1;
    const int m0 = blockIdx.y * BM, n0 = blockIdx.x * BNT;

    auto stA  = [&](int s) -> bf16* { return smem + s * SSET; };
    auto stB  = [&](int s) -> bf16* { return smem + s * SSET + A_ELE; };
    auto stAl = [&](int s) -> bf16* { return smem + s * SSET + A_ELE + B_ELE; };
    auto stBl = [&](int s) -> bf16* { return smem + s * SSET + 2 * A_ELE + B_ELE; };

    auto load_tile = [&](int s, int kt) {
        const size_t kof = (size_t)kt * BK;
#pragma unroll
        for (int i = 0; i < 4; i++) {              // A: 128 rows x 8 chunks of 16B
            const int ch = tid + i * NTH;
            const int r = ch >> 3, c = (ch & 7) * 8;
            const size_t go = (size_t)(m0 + r) * K + kof + c;
            cpa(sptr(stA(s) + r * LDA + c), Ah + go);
            if constexpr (SPLIT) cpa(sptr(stAl(s) + r * LDA + c), Al + go);
        }
#pragma unroll
        for (int i = 0; i < 4; i++) {              // B: 64 rows x 16 chunks of 16B
            const int ch = tid + i * NTH;
            const int r = ch >> 4, c = (ch & 15) * 8;
            const size_t go = (kof + r) * (size_t)N + n0 + c;
            cpa(sptr(stB(s) + r * LDB + c), Bh + go);
            if constexpr (SPLIT) cpa(sptr(stBl(s) + r * LDB + c), Bl + go);
        }
    };

    float acc[2][8][4] = {};

    const int KT = K / BK;
    for (int s = 0; s < STAGES - 1; s++) { load_tile(s, s); cpc(); }

    for (int kt = 0; kt < KT; kt++) {
        cpw<STAGES - 2>();
        __syncthreads();
        const int nkt = kt + STAGES - 1;
        if (nkt < KT) load_tile(nkt % STAGES, nkt);
        cpc();

        const int rs = kt % STAGES;
        const bf16* aS  = stA(rs);
        const bf16* bS  = stB(rs);
        const bf16* aSl = stAl(rs);
        const bf16* bSl = stBl(rs);

#pragma unroll
        for (int ks = 0; ks < BK; ks += 16) {
            uint32_t aH[2][4], bH[8][2];
            uint32_t aL[SPLIT ? 2 : 1][4], bL[SPLIT ? 8 : 1][2];
#pragma unroll
            for (int mt = 0; mt < 2; mt++) {
                const int r = wm * 32 + mt * 16 + (lane & 15);
                const int c = ks + ((lane >> 4) << 3);
                ldm4(aH[mt], sptr(aS + r * LDA + c));
                if constexpr (SPLIT) ldm4(aL[mt], sptr(aSl + r * LDA + c));
            }
#pragma unroll
            for (int np = 0; np < 4; np++) {
                const int r = ks + (((lane >> 3) & 1) << 3) + (lane & 7);
                const int c = wn * 64 + np * 16 + ((lane >> 4) << 3);
                uint32_t t[4];
                ldm4t(t, sptr(bS + r * LDB + c));
                bH[np * 2][0] = t[0]; bH[np * 2][1] = t[1];
                bH[np * 2 + 1][0] = t[2]; bH[np * 2 + 1][1] = t[3];
                if constexpr (SPLIT) {
                    ldm4t(t, sptr(bSl + r * LDB + c));
                    bL[np * 2][0] = t[0]; bL[np * 2][1] = t[1];
                    bL[np * 2 + 1][0] = t[2]; bL[np * 2 + 1][1] = t[3];
                }
            }
#pragma unroll
            for (int mt = 0; mt < 2; mt++)
#pragma unroll
                for (int nt = 0; nt < 8; nt++) {
                    mma16816(acc[mt][nt], aH[mt], bH[nt]);
                    if constexpr (SPLIT) {
                        mma16816(acc[mt][nt], aH[mt], bL[nt]);
                        mma16816(acc[mt][nt], aL[mt], bH[nt]);
                    }
                }
        }
    }

    // ---- epilogue ----
#pragma unroll
    for (int mt = 0; mt < 2; mt++) {
        const int row = m0 + wm * 32 + mt * 16 + (lane >> 2);
#pragma unroll
        for (int nt = 0; nt < 8; nt++) {
            const int col = n0 + wn * 64 + nt * 8 + ((lane & 3) << 1);
            const float2 bs = *reinterpret_cast<const float2*>(bias + col);
            float v0 = acc[mt][nt][0] + bs.x;
            float v1 = acc[mt][nt][1] + bs.y;
            float v2 = acc[mt][nt][2] + bs.x;
            float v3 = acc[mt][nt][3] + bs.y;
            const size_t o0 = (size_t)row * N + col;
            const size_t o1 = (size_t)(row + 8) * N + col;

            if constexpr (MODE == 1) {
                const float2 m2 = *reinterpret_cast<const float2*>(mn + col);
                const float2 i2 = *reinterpret_cast<const float2*>(iv + col);
                const float2 t2 = *reinterpret_cast<const float2*>(bt + col);
                v0 = fmaxf((v0 - m2.x) * i2.x + t2.x, 0.f);
                v1 = fmaxf((v1 - m2.y) * i2.y + t2.y, 0.f);
                v2 = fmaxf((v2 - m2.x) * i2.x + t2.x, 0.f);
                v3 = fmaxf((v3 - m2.y) * i2.y + t2.y, 0.f);
                *reinterpret_cast<uint32_t*>(Cb + o0) = packbf(v0, v1);
                *reinterpret_cast<uint32_t*>(Cb + o1) = packbf(v2, v3);
            } else if constexpr (MODE == 2) {
                *reinterpret_cast<uint32_t*>(Cb + o0) = packbf(v0, v1);
                *reinterpret_cast<uint32_t*>(Cb + o1) = packbf(v2, v3);
                if (Ab) {
                    const float2 m2 = *reinterpret_cast<const float2*>(mn + col);
                    const float2 i2 = *reinterpret_cast<const float2*>(iv + col);
                    const float2 t2 = *reinterpret_cast<const float2*>(bt + col);
                    const float2 y0 = *reinterpret_cast<const float2*>(yin + o0);
                    const float2 y1 = *reinterpret_cast<const float2*>(yin + o1);
                    float a0 = fmaxf((y0.x + cnext * v0 - m2.x) * i2.x + t2.x, 0.f);
                    float a1 = fmaxf((y0.y + cnext * v1 - m2.y) * i2.y + t2.y, 0.f);
                    float a2 = fmaxf((y1.x + cnext * v2 - m2.x) * i2.x + t2.x, 0.f);
                    float a3 = fmaxf((y1.y + cnext * v3 - m2.y) * i2.y + t2.y, 0.f);
                    *reinterpret_cast<uint32_t*>(Ab + o0) = packbf(a0, a1);
                    *reinterpret_cast<uint32_t*>(Ab + o1) = packbf(a2, a3);
                }
            } else {   // MODE 0
                *reinterpret_cast<float2*>(Cf + o0) = make_float2(v0, v1);
                *reinterpret_cast<float2*>(Cf + o1) = make_float2(v2, v3);
                if (Ab) {
                    const float2 m2 = *reinterpret_cast<const float2*>(mn + col);
                    const float2 i2 = *reinterpret_cast<const float2*>(iv + col);
                    const float2 t2 = *reinterpret_cast<const float2*>(bt + col);
                    float a0 = fmaxf((v0 - m2.x) * i2.x + t2.x, 0.f);
                    float a1 = fmaxf((v1 - m2.y) * i2.y + t2.y, 0.f);
                    float a2 = fmaxf((v2 - m2.x) * i2.x + t2.x, 0.f);
                    float a3 = fmaxf((v3 - m2.y) * i2.y + t2.y, 0.f);
                    *reinterpret_cast<uint32_t*>(Ab + o0) = packbf(a0, a1);
                    *reinterpret_cast<uint32_t*>(Ab + o1) = packbf(a2, a3);
                }
            }
        }
    }
}

// ---------------- elementwise kernels ----------------
__global__ void prep_inv(const float* __restrict__ gamma, const float* __restrict__ var,
                         float* __restrict__ inv, int n)
{
    int i = blockIdx.x * blockDim.x + threadIdx.x;
    if (i < n) inv[i] = gamma[i] * rsqrtf(var[i] + BN_EPS);
}

__global__ void conv_bf16(const float* __restrict__ in, bf16* __restrict__ out, int n4)
{
    int i = blockIdx.x * blockDim.x + threadIdx.x;
    if (i >= n4) return;
    float4 v = reinterpret_cast<const float4*>(in)[i];
    uint2 o;
    o.x = packbf(v.x, v.y);
    o.y = packbf(v.z, v.w);
    reinterpret_cast<uint2*>(out)[i] = o;
}

__global__ void conv_split(const float* __restrict__ in,
                           bf16* __restrict__ hi, bf16* __restrict__ lo, int n4)
{
    int i = blockIdx.x * blockDim.x + threadIdx.x;
    if (i >= n4) return;
    float4 v = reinterpret_cast<const float4*>(in)[i];
    float h0 = bf16_round(v.x), h1 = bf16_round(v.y), h2 = bf16_round(v.z), h3 = bf16_round(v.w);
    uint2 uh, ul;
    uh.x = packbf(h0, h1); uh.y = packbf(h2, h3);
    ul.x = packbf(v.x - h0, v.y - h1); ul.y = packbf(v.z - h2, v.w - h3);
    reinterpret_cast<uint2*>(hi)[i] = uh;
    reinterpret_cast<uint2*>(lo)[i] = ul;
}

DEV void unp4(uint2 u, float f[4]) {
    __nv_bfloat162 a = *reinterpret_cast<__nv_bfloat162*>(&u.x);
    __nv_bfloat162 b = *reinterpret_cast<__nv_bfloat162*>(&u.y);
    f[0] = __low2float(a); f[1] = __high2float(a);
    f[2] = __low2float(b); f[3] = __high2float(b);
}

// y += s*(k1 + 2k2 + 2k3 + k4); optional relu; then either emit a0 = relu(bn(y))
// for the next RK step, or (final) emit the hi/lo bf16 split of y.
__global__ void rk4_up(float* __restrict__ y,
                       const bf16* __restrict__ k1, const bf16* __restrict__ k2,
                       const bf16* __restrict__ k3, const bf16* __restrict__ k4,
                       float s, int do_relu,
                       const float* __restrict__ mn, const float* __restrict__ iv,
                       const float* __restrict__ bt,
                       bf16* __restrict__ a_out,
                       bf16* __restrict__ yh, bf16* __restrict__ yl, int n4)
{
    int i = blockIdx.x * blockDim.x + threadIdx.x;
    if (i >= n4) return;
    float4 yv = reinterpret_cast<float4*>(y)[i];
    float f1[4], f2[4], f3[4], f4[4];
    unp4(reinterpret_cast<const uint2*>(k1)[i], f1);
    unp4(reinterpret_cast<const uint2*>(k2)[i], f2);
    unp4(reinterpret_cast<const uint2*>(k3)[i], f3);
    unp4(reinterpret_cast<const uint2*>(k4)[i], f4);
    yv.x += s * (f1[0] + 2.f * (f2[0] + f3[0]) + f4[0]);
    yv.y += s * (f1[1] + 2.f * (f2[1] + f3[1]) + f4[1]);
    yv.z += s * (f1[2] + 2.f * (f2[2] + f3[2]) + f4[2]);
    yv.w += s * (f1[3] + 2.f * (f2[3] + f3[3]) + f4[3]);
    if (do_relu) {
        yv.x = fmaxf(yv.x, 0.f); yv.y = fmaxf(yv.y, 0.f);
        yv.z = fmaxf(yv.z, 0.f); yv.w = fmaxf(yv.w, 0.f);
    }
    reinterpret_cast<float4*>(y)[i] = yv;

    const int col = (i * 4) & (HDIM - 1);
    if (a_out) {
        const float4 m4 = *reinterpret_cast<const float4*>(mn + col);
        const float4 i4 = *reinterpret_cast<const float4*>(iv + col);
        const float4 t4 = *reinterpret_cast<const float4*>(bt + col);
        uint2 o;
        o.x = packbf(fmaxf((yv.x - m4.x) * i4.x + t4.x, 0.f),
                     fmaxf((yv.y - m4.y) * i4.y + t4.y, 0.f));
        o.y = packbf(fmaxf((yv.z - m4.z) * i4.z + t4.z, 0.f),
                     fmaxf((yv.w - m4.w) * i4.w + t4.w, 0.f));
        reinterpret_cast<uint2*>(a_out)[i] = o;
    }
    if (yh) {
        float h0 = bf16_round(yv.x), h1 = bf16_round(yv.y);
        float h2 = bf16_round(yv.z), h3 = bf16_round(yv.w);
        uint2 uh, ul;
        uh.x = packbf(h0, h1); uh.y = packbf(h2, h3);
        ul.x = packbf(yv.x - h0, yv.y - h1);
        ul.y = packbf(yv.z - h2, yv.w - h3);
        reinterpret_cast<uint2*>(yh)[i] = uh;
        reinterpret_cast<uint2*>(yl)[i] = ul;
    }
}

// ---------------- host ----------------
extern "C" void kernel_launch(void* const* d_in, const int* in_sizes, int n_in,
                              void* d_out, int out_size)
{
    const float* X        = (const float*)d_in[0];
    const float* W_in     = (const float*)d_in[1];
    const float* b_in     = (const float*)d_in[2];
    const float* bn_gamma = (const float*)d_in[3];
    const float* bn_beta  = (const float*)d_in[4];
    const float* bn_mean  = (const float*)d_in[5];
    const float* bn_var   = (const float*)d_in[6];
    const float* W1       = (const float*)d_in[7];
    const float* b1       = (const float*)d_in[8];
    const float* W2       = (const float*)d_in[9];
    const float* b2       = (const float*)d_in[10];
    const float* W_out    = (const float*)d_in[11];
    const float* b_out    = (const float*)d_in[12];

    float *y, *inv;
    bf16 *a, *h, *kbase, *yh, *yl, *xh, *xl, *w1b, *w2b, *wih, *wil, *woh, *wol;
    cudaGetSymbolAddress((void**)&y,   g_y);
    cudaGetSymbolAddress((void**)&inv, g_inv);
    cudaGetSymbolAddress((void**)&a,   g_a);
    cudaGetSymbolAddress((void**)&h,   g_h);
    cudaGetSymbolAddress((void**)&kbase, g_k);
    cudaGetSymbolAddress((void**)&yh,  g_yh);
    cudaGetSymbolAddress((void**)&yl,  g_yl);
    cudaGetSymbolAddress((void**)&xh,  g_xh);
    cudaGetSymbolAddress((void**)&xl,  g_xl);
    cudaGetSymbolAddress((void**)&w1b, g_w1);
    cudaGetSymbolAddress((void**)&w2b, g_w2);
    cudaGetSymbolAddress((void**)&wih, g_wih);
    cudaGetSymbolAddress((void**)&wil, g_wil);
    cudaGetSymbolAddress((void**)&woh, g_woh);
    cudaGetSymbolAddress((void**)&wol, g_wol);
    bf16* kb[4];
    for (int i = 0; i < 4; i++) kb[i] = kbase + (size_t)i * BATCH * HDIM;

    cudaFuncSetAttribute(gemm_bf16<0, 2>, cudaFuncAttributeMaxDynamicSharedMemorySize, SPLIT_SMEM);
    cudaFuncSetAttribute(gemm_bf16<1, 3>, cudaFuncAttributeMaxDynamicSharedMemorySize, PLAIN_SMEM);
    cudaFuncSetAttribute(gemm_bf16<2, 3>, cudaFuncAttributeMaxDynamicSharedMemorySize, PLAIN_SMEM);

    // ---- prep ----
    prep_inv<<<(NBLK * 2 * HDIM + 255) / 256, 256>>>(bn_gamma, bn_var, inv, NBLK * 2 * HDIM);
    conv_split<<<(BATCH * INDIM / 4 + 255) / 256, 256>>>(X, xh, xl, BATCH * INDIM / 4);
    conv_split<<<(INDIM * HDIM / 4 + 255) / 256, 256>>>(W_in, wih, wil, INDIM * HDIM / 4);
    conv_split<<<(HDIM * OUTDIM / 4 + 255) / 256, 256>>>(W_out, woh, wol, HDIM * OUTDIM / 4);
    conv_bf16<<<(NBLK * HDIM * HDIM / 4 + 255) / 256, 256>>>(W1, w1b, NBLK * HDIM * HDIM / 4);
    conv_bf16<<<(NBLK * HDIM * HDIM / 4 + 255) / 256, 256>>>(W2, w2b, NBLK * HDIM * HDIM / 4);

    const dim3 blk(NTH);
    const dim3 gH(HDIM / BNT, BATCH / BM);     // (8, 128)
    const dim3 gO(OUTDIM / BNT, BATCH / BM);   // (4, 128)

    const float* mn00 = bn_mean;               // block 0, bn0
    const float* bt00 = bn_beta;
    const float* iv00 = inv;

    // ---- prologue: y = X@W_in + b_in (split), also a0 = relu(bn0_b0(y)) ----
    gemm_bf16<0, 2><<<gH, blk, SPLIT_SMEM>>>(xh, xl, wih, wil, b_in,
                                             mn00, iv00, bt00, nullptr, 0.f,
                                             y, nullptr, a, BATCH, INDIM, HDIM);

    const float hstep = 0.5f;                  // 2 RK4 steps per block
    const float cn[3] = {0.5f * hstep, 0.5f * hstep, hstep};
    const int n4 = BATCH * HDIM / 4;

    for (int b = 0; b < NBLK; ++b) {
        const bf16* W1p = w1b + (size_t)b * HDIM * HDIM;
        const bf16* W2p = w2b + (size_t)b * HDIM * HDIM;
        const float* b1p = b1 + b * HDIM;
        const float* b2p = b2 + b * HDIM;
        const float* mn0 = bn_mean + (size_t)(b * 2 + 0) * HDIM;
        const float* mn1 = bn_mean + (size_t)(b * 2 + 1) * HDIM;
        const float* bt0 = bn_beta + (size_t)(b * 2 + 0) * HDIM;
        const float* bt1 = bn_beta + (size_t)(b * 2 + 1) * HDIM;
        const float* iv0 = inv + (b * 2 + 0) * HDIM;
        const float* iv1 = inv + (b * 2 + 1) * HDIM;

        for (int s = 0; s < 2; ++s) {
            for (int st = 0; st < 4; ++st) {
                gemm_bf16<1, 3><<<gH, blk, PLAIN_SMEM>>>(a, nullptr, W1p, nullptr, b1p,
                                                         mn1, iv1, bt1, nullptr, 0.f,
                                                         nullptr, h, nullptr,
                                                         BATCH, HDIM, HDIM);
                const bool last = (st == 3);
                gemm_bf16<2, 3><<<gH, blk, PLAIN_SMEM>>>(h, nullptr, W2p, nullptr, b2p,
                                                         mn0, iv0, bt0, y, last ? 0.f : cn[st],
                                                         nullptr, kb[st], last ? nullptr : a,
                                                         BATCH, HDIM, HDIM);
            }
            const bool block_end = (s == 1);
            const bool final_end = block_end && (b == NBLK - 1);
            const float* mnN; const float* ivN; const float* btN;
            if (block_end) {   // next is the following block's bn0 (unused when final)
                mnN = bn_mean + (size_t)((b + 1) * 2 % (NBLK * 2)) * HDIM;
                btN = bn_beta + (size_t)((b + 1) * 2 % (NBLK * 2)) * HDIM;
                ivN = inv + ((b + 1) * 2 % (NBLK * 2)) * HDIM;
            } else {           // same block's bn0 for the next RK step
                mnN = mn0; btN = bt0; ivN = iv0;
            }
            rk4_up<<<(n4 + 255) / 256, 256>>>(y, kb[0], kb[1], kb[2], kb[3],
                                              hstep / 6.f, block_end ? 1 : 0,
                                              mnN, ivN, btN,
                                              final_end ? nullptr : a,
                                              final_end ? yh : nullptr,
                                              final_end ? yl : nullptr, n4);
        }
    }

    // ---- epilogue: out = y @ W_out + b_out (split, y pre-split in rk4) ----
    gemm_bf16<0, 2><<<gO, blk, SPLIT_SMEM>>>(yh, yl, woh, wol, b_out,
                                             nullptr, nullptr, nullptr, nullptr, 0.f,
                                             (float*)d_out, nullptr, nullptr,
                                             BATCH, HDIM, OUTDIM);
}

// round 6
// speedup vs baseline: 6.6957x; 3.2626x over previous
#include <cuda_runtime.h>
#include <cuda_bf16.h>
#include <cstdint>
#include <cstddef>

#define DEV __device__ __forceinline__
using bf16 = __nv_bfloat16;

// ---------------- problem constants ----------------
constexpr int BATCH  = 16384;
constexpr int HDIM   = 1024;
constexpr int INDIM  = 512;
constexpr int OUTDIM = 512;
constexpr int NBLK   = 2;
constexpr float BN_EPS = 1e-3f;

// ---------------- GEMM tiling ----------------
constexpr int BM  = 128;
constexpr int BNT = 128;
constexpr int BK  = 64;
constexpr int NTH = 256;          // 8 warps: 4 (m) x 2 (n); warp tile 32x64
constexpr int LDA = BK + 8;       // 72  -> conflict-free ldmatrix
constexpr int LDB = BNT + 8;      // 136
constexpr int A_ELE = BM * LDA;
constexpr int B_ELE = BK * LDB;
constexpr int PLAIN_SMEM = 3 * (A_ELE + B_ELE) * 2;       // 107,520 B (3 stages)
constexpr int SPLIT_SMEM = 2 * 2 * (A_ELE + B_ELE) * 2;   // 143,360 B (2 stages, hi+lo)

// ---------------- persistent device scratch ----------------
__device__ __align__(16) float g_y [BATCH * HDIM];
__device__ __align__(16) bf16  g_a [BATCH * HDIM];
__device__ __align__(16) bf16  g_h [BATCH * HDIM];
__device__ __align__(16) bf16  g_yh[BATCH * HDIM];
__device__ __align__(16) bf16  g_yl[BATCH * HDIM];
__device__ __align__(16) bf16  g_xh[BATCH * INDIM];
__device__ __align__(16) bf16  g_xl[BATCH * INDIM];
__device__ __align__(16) bf16  g_w1[NBLK * HDIM * HDIM];
__device__ __align__(16) bf16  g_w2[NBLK * HDIM * HDIM];
__device__ __align__(16) bf16  g_wih[INDIM * HDIM];
__device__ __align__(16) bf16  g_wil[INDIM * HDIM];
__device__ __align__(16) bf16  g_woh[HDIM * OUTDIM];
__device__ __align__(16) bf16  g_wol[HDIM * OUTDIM];
__device__ __align__(16) float g_inv[NBLK * 2 * HDIM];

// ---------------- small helpers ----------------
DEV uint32_t sptr(const void* p) { return (uint32_t)__cvta_generic_to_shared(p); }

DEV void ldm4(uint32_t r[4], uint32_t a) {
    asm volatile("ldmatrix.sync.aligned.m8n8.x4.shared.b16 {%0,%1,%2,%3}, [%4];"
                 : "=r"(r[0]), "=r"(r[1]), "=r"(r[2]), "=r"(r[3]) : "r"(a));
}
DEV void ldm4t(uint32_t r[4], uint32_t a) {
    asm volatile("ldmatrix.sync.aligned.m8n8.x4.trans.shared.b16 {%0,%1,%2,%3}, [%4];"
                 : "=r"(r[0]), "=r"(r[1]), "=r"(r[2]), "=r"(r[3]) : "r"(a));
}
DEV void mma16816(float d[4], const uint32_t a[4], const uint32_t b[2]) {
    asm volatile("mma.sync.aligned.m16n8k16.row.col.f32.bf16.bf16.f32 "
                 "{%0,%1,%2,%3}, {%4,%5,%6,%7}, {%8,%9}, {%0,%1,%2,%3};"
                 : "+f"(d[0]), "+f"(d[1]), "+f"(d[2]), "+f"(d[3])
                 : "r"(a[0]), "r"(a[1]), "r"(a[2]), "r"(a[3]), "r"(b[0]), "r"(b[1]));
}
DEV uint32_t packbf(float a, float b) {
    __nv_bfloat162 t = __floats2bfloat162_rn(a, b);
    return *reinterpret_cast<uint32_t*>(&t);
}
DEV float bf16_round(float v) { return __bfloat162float(__float2bfloat16_rn(v)); }

DEV void cpa(uint32_t dst, const void* src) {
    asm volatile("cp.async.cg.shared.global [%0], [%1], 16;\n" :: "r"(dst), "l"(src));
}
DEV void cpc() { asm volatile("cp.async.commit_group;\n"); }
template <int N> DEV void cpw() { asm volatile("cp.async.wait_group %0;\n" :: "n"(N)); }

// ---------------- unified pipelined bf16 GEMM ----------------
// A: [M,K] bf16, B: [K,N] bf16.
// MODE 0 (SPLIT): acc = Ah·Bh + Ah·Bl + Al·Bh; v = acc+bias; Cf = v fp32;
//                 if Ab: Ab = relu(bn(v))                       [prologue/epilogue]
// MODE 1: v = acc+bias; Cb = relu(bn(v)) bf16                   [ODE GEMM #1 -> h]
// MODE 2: v = acc+bias (k1); Ab = relu(bn(yin + cnext*v))       [midpoint activation]
// MODE 3: v = acc+bias (k2); t = relu(yin + v);                 [block finish]
//         if Cf: Cf = t; if Ab: Ab = relu(bn(t)); if Yh: Yh/Yl = split(t)
template <int MODE, int STAGES>
__global__ void __launch_bounds__(NTH, (MODE == 0) ? 1 : 2)
gemm_bf16(const bf16* __restrict__ Ah, const bf16* __restrict__ Al,
          const bf16* __restrict__ Bh, const bf16* __restrict__ Bl,
          const float* __restrict__ bias,
          const float* __restrict__ mn, const float* __restrict__ iv, const float* __restrict__ bt,
          const float* __restrict__ yin, float cnext,
          float* __restrict__ Cf, bf16* __restrict__ Cb, bf16* __restrict__ Ab,
          bf16* __restrict__ Yh, bf16* __restrict__ Yl,
          int M, int K, int N)
{
    constexpr bool SPLIT = (MODE == 0);
    constexpr int SSET = (A_ELE + B_ELE) * (SPLIT ? 2 : 1);
    extern __shared__ __align__(16) bf16 smem[];

    const int tid = threadIdx.x, lane = tid & 31, warp = tid >> 5;
    const int wm = warp >> 1, wn = warp & 1;
    const int m0 = blockIdx.y * BM, n0 = blockIdx.x * BNT;

    auto stA  = [&](int s) -> bf16* { return smem + s * SSET; };
    auto stB  = [&](int s) -> bf16* { return smem + s * SSET + A_ELE; };
    auto stAl = [&](int s) -> bf16* { return smem + s * SSET + A_ELE + B_ELE; };
    auto stBl = [&](int s) -> bf16* { return smem + s * SSET + 2 * A_ELE + B_ELE; };

    auto load_tile = [&](int s, int kt) {
        const size_t kof = (size_t)kt * BK;
#pragma unroll
        for (int i = 0; i < 4; i++) {              // A: 128 rows x 8 chunks of 16B
            const int ch = tid + i * NTH;
            const int r = ch >> 3, c = (ch & 7) * 8;
            const size_t go = (size_t)(m0 + r) * K + kof + c;
            cpa(sptr(stA(s) + r * LDA + c), Ah + go);
            if constexpr (SPLIT) cpa(sptr(stAl(s) + r * LDA + c), Al + go);
        }
#pragma unroll
        for (int i = 0; i < 4; i++) {              // B: 64 rows x 16 chunks of 16B
            const int ch = tid + i * NTH;
            const int r = ch >> 4, c = (ch & 15) * 8;
            const size_t go = (kof + r) * (size_t)N + n0 + c;
            cpa(sptr(stB(s) + r * LDB + c), Bh + go);
            if constexpr (SPLIT) cpa(sptr(stBl(s) + r * LDB + c), Bl + go);
        }
    };

    float acc[2][8][4] = {};

    const int KT = K / BK;
    for (int s = 0; s < STAGES - 1; s++) { load_tile(s, s); cpc(); }

    for (int kt = 0; kt < KT; kt++) {
        cpw<STAGES - 2>();
        __syncthreads();
        const int nkt = kt + STAGES - 1;
        if (nkt < KT) load_tile(nkt % STAGES, nkt);
        cpc();

        const int rs = kt % STAGES;
        const bf16* aS  = stA(rs);
        const bf16* bS  = stB(rs);

        if constexpr (!SPLIT) {
            // ---- register double-buffered fragment pipeline ----
            uint32_t aF[2][2][4], bF[2][8][2];
            auto ldf = [&](int bb, int ks) {
#pragma unroll
                for (int mt = 0; mt < 2; mt++) {
                    const int r = wm * 32 + mt * 16 + (lane & 15);
                    const int c = ks + ((lane >> 4) << 3);
                    ldm4(aF[bb][mt], sptr(aS + r * LDA + c));
                }
#pragma unroll
                for (int np = 0; np < 4; np++) {
                    const int r = ks + (((lane >> 3) & 1) << 3) + (lane & 7);
                    const int c = wn * 64 + np * 16 + ((lane >> 4) << 3);
                    uint32_t t[4];
                    ldm4t(t, sptr(bS + r * LDB + c));
                    bF[bb][np * 2][0] = t[0]; bF[bb][np * 2][1] = t[1];
                    bF[bb][np * 2 + 1][0] = t[2]; bF[bb][np * 2 + 1][1] = t[3];
                }
            };
            ldf(0, 0);
#pragma unroll
            for (int ksi = 0; ksi < BK / 16; ksi++) {
                if (ksi + 1 < BK / 16) ldf((ksi + 1) & 1, (ksi + 1) * 16);
                const int cur = ksi & 1;
#pragma unroll
                for (int mt = 0; mt < 2; mt++)
#pragma unroll
                    for (int nt = 0; nt < 8; nt++)
                        mma16816(acc[mt][nt], aF[cur][mt], bF[cur][nt]);
            }
        } else {
            const bf16* aSl = stAl(rs);
            const bf16* bSl = stBl(rs);
#pragma unroll
            for (int ks = 0; ks < BK; ks += 16) {
                uint32_t aH[2][4], bH[8][2], aL[2][4], bL[8][2];
#pragma unroll
                for (int mt = 0; mt < 2; mt++) {
                    const int r = wm * 32 + mt * 16 + (lane & 15);
                    const int c = ks + ((lane >> 4) << 3);
                    ldm4(aH[mt], sptr(aS + r * LDA + c));
                    ldm4(aL[mt], sptr(aSl + r * LDA + c));
                }
#pragma unroll
                for (int np = 0; np < 4; np++) {
                    const int r = ks + (((lane >> 3) & 1) << 3) + (lane & 7);
                    const int c = wn * 64 + np * 16 + ((lane >> 4) << 3);
                    uint32_t t[4];
                    ldm4t(t, sptr(bS + r * LDB + c));
                    bH[np * 2][0] = t[0]; bH[np * 2][1] = t[1];
                    bH[np * 2 + 1][0] = t[2]; bH[np * 2 + 1][1] = t[3];
                    ldm4t(t, sptr(bSl + r * LDB + c));
                    bL[np * 2][0] = t[0]; bL[np * 2][1] = t[1];
                    bL[np * 2 + 1][0] = t[2]; bL[np * 2 + 1][1] = t[3];
                }
#pragma unroll
                for (int mt = 0; mt < 2; mt++)
#pragma unroll
                    for (int nt = 0; nt < 8; nt++) {
                        mma16816(acc[mt][nt], aH[mt], bH[nt]);
                        mma16816(acc[mt][nt], aH[mt], bL[nt]);
                        mma16816(acc[mt][nt], aL[mt], bH[nt]);
                    }
            }
        }
        __syncthreads();
    }

    // ---- epilogue ----
#pragma unroll
    for (int mt = 0; mt < 2; mt++) {
        const int row = m0 + wm * 32 + mt * 16 + (lane >> 2);
#pragma unroll
        for (int nt = 0; nt < 8; nt++) {
            const int col = n0 + wn * 64 + nt * 8 + ((lane & 3) << 1);
            const float2 bs = *reinterpret_cast<const float2*>(bias + col);
            float v0 = acc[mt][nt][0] + bs.x;
            float v1 = acc[mt][nt][1] + bs.y;
            float v2 = acc[mt][nt][2] + bs.x;
            float v3 = acc[mt][nt][3] + bs.y;
            const size_t o0 = (size_t)row * N + col;
            const size_t o1 = (size_t)(row + 8) * N + col;

            if constexpr (MODE == 1) {
                const float2 m2 = *reinterpret_cast<const float2*>(mn + col);
                const float2 i2 = *reinterpret_cast<const float2*>(iv + col);
                const float2 t2 = *reinterpret_cast<const float2*>(bt + col);
                v0 = fmaxf((v0 - m2.x) * i2.x + t2.x, 0.f);
                v1 = fmaxf((v1 - m2.y) * i2.y + t2.y, 0.f);
                v2 = fmaxf((v2 - m2.x) * i2.x + t2.x, 0.f);
                v3 = fmaxf((v3 - m2.y) * i2.y + t2.y, 0.f);
                *reinterpret_cast<uint32_t*>(Cb + o0) = packbf(v0, v1);
                *reinterpret_cast<uint32_t*>(Cb + o1) = packbf(v2, v3);
            } else if constexpr (MODE == 2) {
                const float2 m2 = *reinterpret_cast<const float2*>(mn + col);
                const float2 i2 = *reinterpret_cast<const float2*>(iv + col);
                const float2 t2 = *reinterpret_cast<const float2*>(bt + col);
                const float2 y0 = *reinterpret_cast<const float2*>(yin + o0);
                const float2 y1 = *reinterpret_cast<const float2*>(yin + o1);
                float a0 = fmaxf((y0.x + cnext * v0 - m2.x) * i2.x + t2.x, 0.f);
                float a1 = fmaxf((y0.y + cnext * v1 - m2.y) * i2.y + t2.y, 0.f);
                float a2 = fmaxf((y1.x + cnext * v2 - m2.x) * i2.x + t2.x, 0.f);
                float a3 = fmaxf((y1.y + cnext * v3 - m2.y) * i2.y + t2.y, 0.f);
                *reinterpret_cast<uint32_t*>(Ab + o0) = packbf(a0, a1);
                *reinterpret_cast<uint32_t*>(Ab + o1) = packbf(a2, a3);
            } else if constexpr (MODE == 3) {
                const float2 y0 = *reinterpret_cast<const float2*>(yin + o0);
                const float2 y1 = *reinterpret_cast<const float2*>(yin + o1);
                float t0 = fmaxf(y0.x + v0, 0.f);
                float t1 = fmaxf(y0.y + v1, 0.f);
                float t2v = fmaxf(y1.x + v2, 0.f);
                float t3 = fmaxf(y1.y + v3, 0.f);
                if (Cf) {
                    *reinterpret_cast<float2*>(Cf + o0) = make_float2(t0, t1);
                    *reinterpret_cast<float2*>(Cf + o1) = make_float2(t2v, t3);
                }
                if (Ab) {
                    const float2 m2 = *reinterpret_cast<const float2*>(mn + col);
                    const float2 i2 = *reinterpret_cast<const float2*>(iv + col);
                    const float2 b2v = *reinterpret_cast<const float2*>(bt + col);
                    float a0 = fmaxf((t0 - m2.x) * i2.x + b2v.x, 0.f);
                    float a1 = fmaxf((t1 - m2.y) * i2.y + b2v.y, 0.f);
                    float a2 = fmaxf((t2v - m2.x) * i2.x + b2v.x, 0.f);
                    float a3 = fmaxf((t3 - m2.y) * i2.y + b2v.y, 0.f);
                    *reinterpret_cast<uint32_t*>(Ab + o0) = packbf(a0, a1);
                    *reinterpret_cast<uint32_t*>(Ab + o1) = packbf(a2, a3);
                }
                if (Yh) {
                    float h0 = bf16_round(t0), h1 = bf16_round(t1);
                    float h2 = bf16_round(t2v), h3 = bf16_round(t3);
                    *reinterpret_cast<uint32_t*>(Yh + o0) = packbf(h0, h1);
                    *reinterpret_cast<uint32_t*>(Yh + o1) = packbf(h2, h3);
                    *reinterpret_cast<uint32_t*>(Yl + o0) = packbf(t0 - h0, t1 - h1);
                    *reinterpret_cast<uint32_t*>(Yl + o1) = packbf(t2v - h2, t3 - h3);
                }
            } else {   // MODE 0
                *reinterpret_cast<float2*>(Cf + o0) = make_float2(v0, v1);
                *reinterpret_cast<float2*>(Cf + o1) = make_float2(v2, v3);
                if (Ab) {
                    const float2 m2 = *reinterpret_cast<const float2*>(mn + col);
                    const float2 i2 = *reinterpret_cast<const float2*>(iv + col);
                    const float2 t2 = *reinterpret_cast<const float2*>(bt + col);
                    float a0 = fmaxf((v0 - m2.x) * i2.x + t2.x, 0.f);
                    float a1 = fmaxf((v1 - m2.y) * i2.y + t2.y, 0.f);
                    float a2 = fmaxf((v2 - m2.x) * i2.x + t2.x, 0.f);
                    float a3 = fmaxf((v3 - m2.y) * i2.y + t2.y, 0.f);
                    *reinterpret_cast<uint32_t*>(Ab + o0) = packbf(a0, a1);
                    *reinterpret_cast<uint32_t*>(Ab + o1) = packbf(a2, a3);
                }
            }
        }
    }
}

// ---------------- elementwise / prep kernels ----------------
__global__ void prep_inv(const float* __restrict__ gamma, const float* __restrict__ var,
                         float* __restrict__ inv, int n)
{
    int i = blockIdx.x * blockDim.x + threadIdx.x;
    if (i < n) inv[i] = gamma[i] * rsqrtf(var[i] + BN_EPS);
}

__global__ void conv_bf16(const float* __restrict__ in, bf16* __restrict__ out, int n4)
{
    int i = blockIdx.x * blockDim.x + threadIdx.x;
    if (i >= n4) return;
    float4 v = reinterpret_cast<const float4*>(in)[i];
    uint2 o;
    o.x = packbf(v.x, v.y);
    o.y = packbf(v.z, v.w);
    reinterpret_cast<uint2*>(out)[i] = o;
}

__global__ void conv_split(const float* __restrict__ in,
                           bf16* __restrict__ hi, bf16* __restrict__ lo, int n4)
{
    int i = blockIdx.x * blockDim.x + threadIdx.x;
    if (i >= n4) return;
    float4 v = reinterpret_cast<const float4*>(in)[i];
    float h0 = bf16_round(v.x), h1 = bf16_round(v.y), h2 = bf16_round(v.z), h3 = bf16_round(v.w);
    uint2 uh, ul;
    uh.x = packbf(h0, h1); uh.y = packbf(h2, h3);
    ul.x = packbf(v.x - h0, v.y - h1); ul.y = packbf(v.z - h2, v.w - h3);
    reinterpret_cast<uint2*>(hi)[i] = uh;
    reinterpret_cast<uint2*>(lo)[i] = ul;
}

// ---------------- host ----------------
extern "C" void kernel_launch(void* const* d_in, const int* in_sizes, int n_in,
                              void* d_out, int out_size)
{
    const float* X        = (const float*)d_in[0];
    const float* W_in     = (const float*)d_in[1];
    const float* b_in     = (const float*)d_in[2];
    const float* bn_gamma = (const float*)d_in[3];
    const float* bn_beta  = (const float*)d_in[4];
    const float* bn_mean  = (const float*)d_in[5];
    const float* bn_var   = (const float*)d_in[6];
    const float* W1       = (const float*)d_in[7];
    const float* b1       = (const float*)d_in[8];
    const float* W2       = (const float*)d_in[9];
    const float* b2       = (const float*)d_in[10];
    const float* W_out    = (const float*)d_in[11];
    const float* b_out    = (const float*)d_in[12];

    float *y, *inv;
    bf16 *a, *h, *yh, *yl, *xh, *xl, *w1b, *w2b, *wih, *wil, *woh, *wol;
    cudaGetSymbolAddress((void**)&y,   g_y);
    cudaGetSymbolAddress((void**)&inv, g_inv);
    cudaGetSymbolAddress((void**)&a,   g_a);
    cudaGetSymbolAddress((void**)&h,   g_h);
    cudaGetSymbolAddress((void**)&yh,  g_yh);
    cudaGetSymbolAddress((void**)&yl,  g_yl);
    cudaGetSymbolAddress((void**)&xh,  g_xh);
    cudaGetSymbolAddress((void**)&xl,  g_xl);
    cudaGetSymbolAddress((void**)&w1b, g_w1);
    cudaGetSymbolAddress((void**)&w2b, g_w2);
    cudaGetSymbolAddress((void**)&wih, g_wih);
    cudaGetSymbolAddress((void**)&wil, g_wil);
    cudaGetSymbolAddress((void**)&woh, g_woh);
    cudaGetSymbolAddress((void**)&wol, g_wol);

    cudaFuncSetAttribute(gemm_bf16<0, 2>, cudaFuncAttributeMaxDynamicSharedMemorySize, SPLIT_SMEM);
    cudaFuncSetAttribute(gemm_bf16<1, 3>, cudaFuncAttributeMaxDynamicSharedMemorySize, PLAIN_SMEM);
    cudaFuncSetAttribute(gemm_bf16<2, 3>, cudaFuncAttributeMaxDynamicSharedMemorySize, PLAIN_SMEM);
    cudaFuncSetAttribute(gemm_bf16<3, 3>, cudaFuncAttributeMaxDynamicSharedMemorySize, PLAIN_SMEM);

    // ---- prep ----
    prep_inv<<<(NBLK * 2 * HDIM + 255) / 256, 256>>>(bn_gamma, bn_var, inv, NBLK * 2 * HDIM);
    conv_split<<<(BATCH * INDIM / 4 + 255) / 256, 256>>>(X, xh, xl, BATCH * INDIM / 4);
    conv_split<<<(INDIM * HDIM / 4 + 255) / 256, 256>>>(W_in, wih, wil, INDIM * HDIM / 4);
    conv_split<<<(HDIM * OUTDIM / 4 + 255) / 256, 256>>>(W_out, woh, wol, HDIM * OUTDIM / 4);
    conv_bf16<<<(NBLK * HDIM * HDIM / 4 + 255) / 256, 256>>>(W1, w1b, NBLK * HDIM * HDIM / 4);
    conv_bf16<<<(NBLK * HDIM * HDIM / 4 + 255) / 256, 256>>>(W2, w2b, NBLK * HDIM * HDIM / 4);

    const dim3 blk(NTH);
    const dim3 gH(HDIM / BNT, BATCH / BM);     // (8, 128)
    const dim3 gO(OUTDIM / BNT, BATCH / BM);   // (4, 128)

    // ---- prologue: y = X@W_in + b_in (split); a = relu(bn0_b0(y)) ----
    gemm_bf16<0, 2><<<gH, blk, SPLIT_SMEM>>>(xh, xl, wih, wil, b_in,
                                             bn_mean, inv, bn_beta,
                                             nullptr, 0.f,
                                             y, nullptr, a, nullptr, nullptr,
                                             BATCH, INDIM, HDIM);

    // ---- RK2 midpoint per block, fully fused (no k buffers, no update kernels):
    //   a   = relu(bn0(y))                      (from previous epilogue)
    //   h   = relu(bn1(a@W1 + b1))              MODE 1
    //   amid= relu(bn0(y + 0.5*(h@W2+b2)))      MODE 2
    //   h   = relu(bn1(amid@W1 + b1))           MODE 1
    //   y   = relu(y + (h@W2+b2));  a_next / split(y)   MODE 3
    for (int b = 0; b < NBLK; ++b) {
        const bf16* W1p = w1b + (size_t)b * HDIM * HDIM;
        const bf16* W2p = w2b + (size_t)b * HDIM * HDIM;
        const float* b1p = b1 + b * HDIM;
        const float* b2p = b2 + b * HDIM;
        const float* mn0 = bn_mean + (size_t)(b * 2 + 0) * HDIM;
        const float* mn1 = bn_mean + (size_t)(b * 2 + 1) * HDIM;
        const float* bt0 = bn_beta + (size_t)(b * 2 + 0) * HDIM;
        const float* bt1 = bn_beta + (size_t)(b * 2 + 1) * HDIM;
        const float* iv0 = inv + (b * 2 + 0) * HDIM;
        const float* iv1 = inv + (b * 2 + 1) * HDIM;

        // stage 1: h = relu(bn1(a@W1+b1))
        gemm_bf16<1, 3><<<gH, blk, PLAIN_SMEM>>>(a, nullptr, W1p, nullptr, b1p,
                                                 mn1, iv1, bt1, nullptr, 0.f,
                                                 nullptr, h, nullptr, nullptr, nullptr,
                                                 BATCH, HDIM, HDIM);
        // k1 epilogue: amid = relu(bn0(y + 0.5*k1))
        gemm_bf16<2, 3><<<gH, blk, PLAIN_SMEM>>>(h, nullptr, W2p, nullptr, b2p,
                                                 mn0, iv0, bt0, y, 0.5f,
                                                 nullptr, nullptr, a, nullptr, nullptr,
                                                 BATCH, HDIM, HDIM);
        // stage 2: h = relu(bn1(amid@W1+b1))
        gemm_bf16<1, 3><<<gH, blk, PLAIN_SMEM>>>(a, nullptr, W1p, nullptr, b1p,
                                                 mn1, iv1, bt1, nullptr, 0.f,
                                                 nullptr, h, nullptr, nullptr, nullptr,
                                                 BATCH, HDIM, HDIM);
        // k2 epilogue: y = relu(y + k2); emit next activation or output split
        const bool final_blk = (b == NBLK - 1);
        const float* mnN = bn_mean + (size_t)((b + 1) * 2 % (NBLK * 2)) * HDIM;
        const float* btN = bn_beta + (size_t)((b + 1) * 2 % (NBLK * 2)) * HDIM;
        const float* ivN = inv + ((b + 1) * 2 % (NBLK * 2)) * HDIM;
        gemm_bf16<3, 3><<<gH, blk, PLAIN_SMEM>>>(h, nullptr, W2p, nullptr, b2p,
                                                 mnN, ivN, btN, y, 0.f,
                                                 final_blk ? nullptr : y,
                                                 nullptr,
                                                 final_blk ? nullptr : a,
                                                 final_blk ? yh : nullptr,
                                                 final_blk ? yl : nullptr,
                                                 BATCH, HDIM, HDIM);
    }

    // ---- epilogue: out = y @ W_out + b_out (split) ----
    gemm_bf16<0, 2><<<gO, blk, SPLIT_SMEM>>>(yh, yl, woh, wol, b_out,
                                             nullptr, nullptr, nullptr, nullptr, 0.f,
                                             (float*)d_out, nullptr, nullptr, nullptr, nullptr,
                                             BATCH, HDIM, OUTDIM);
}

// round 7
// speedup vs baseline: 8.1870x; 1.2227x over previous
#include <cuda_runtime.h>
#include <cuda_fp16.h>
#include <cstdint>
#include <cstddef>

#define DEV __device__ __forceinline__
using f16 = __half;

// ---------------- problem constants ----------------
constexpr int BATCH  = 16384;
constexpr int HDIM   = 1024;
constexpr int INDIM  = 512;
constexpr int OUTDIM = 512;
constexpr int NBLK   = 2;
constexpr float BN_EPS = 1e-3f;

// ---------------- GEMM tiling ----------------
constexpr int BM  = 128;
constexpr int BNT = 128;
constexpr int BK  = 64;
constexpr int NTH = 256;          // 8 warps: 4 (m) x 2 (n); warp tile 32x64
constexpr int LDA = BK + 8;       // 72  -> conflict-free ldmatrix
constexpr int LDB = BNT + 8;      // 136
constexpr int A_ELE = BM * LDA;
constexpr int B_ELE = BK * LDB;
constexpr int S_PIPE = 3;
constexpr int GEMM_SMEM = S_PIPE * (A_ELE + B_ELE) * 2;   // 107,520 B

// ---------------- persistent device scratch ----------------
__device__ __align__(16) float g_y [BATCH * HDIM];   // fp32 residual stream
__device__ __align__(16) f16   g_a [BATCH * HDIM];   // current activation (GEMM1 input)
__device__ __align__(16) f16   g_h [BATCH * HDIM];   // hidden (GEMM2 input)
__device__ __align__(16) f16   g_yh[BATCH * HDIM];   // fp16 copy of final y (epilogue A)
__device__ __align__(16) f16   g_x [BATCH * INDIM];
__device__ __align__(16) f16   g_w1[NBLK * HDIM * HDIM];
__device__ __align__(16) f16   g_w2[NBLK * HDIM * HDIM];
__device__ __align__(16) f16   g_wi[INDIM * HDIM];
__device__ __align__(16) f16   g_wo[HDIM * OUTDIM];
__device__ __align__(16) float g_inv[NBLK * 2 * HDIM];

// ---------------- small helpers ----------------
DEV uint32_t sptr(const void* p) { return (uint32_t)__cvta_generic_to_shared(p); }

DEV void ldm4(uint32_t r[4], uint32_t a) {
    asm volatile("ldmatrix.sync.aligned.m8n8.x4.shared.b16 {%0,%1,%2,%3}, [%4];"
                 : "=r"(r[0]), "=r"(r[1]), "=r"(r[2]), "=r"(r[3]) : "r"(a));
}
DEV void ldm4t(uint32_t r[4], uint32_t a) {
    asm volatile("ldmatrix.sync.aligned.m8n8.x4.trans.shared.b16 {%0,%1,%2,%3}, [%4];"
                 : "=r"(r[0]), "=r"(r[1]), "=r"(r[2]), "=r"(r[3]) : "r"(a));
}
DEV void mma16816(float d[4], const uint32_t a[4], const uint32_t b[2]) {
    asm volatile("mma.sync.aligned.m16n8k16.row.col.f32.f16.f16.f32 "
                 "{%0,%1,%2,%3}, {%4,%5,%6,%7}, {%8,%9}, {%0,%1,%2,%3};"
                 : "+f"(d[0]), "+f"(d[1]), "+f"(d[2]), "+f"(d[3])
                 : "r"(a[0]), "r"(a[1]), "r"(a[2]), "r"(a[3]), "r"(b[0]), "r"(b[1]));
}
DEV uint32_t packh(float a, float b) {
    __half2 t = __floats2half2_rn(a, b);
    return *reinterpret_cast<uint32_t*>(&t);
}

DEV void cpa(uint32_t dst, const void* src) {
    asm volatile("cp.async.cg.shared.global [%0], [%1], 16;\n" :: "r"(dst), "l"(src));
}
DEV void cpc() { asm volatile("cp.async.commit_group;\n"); }
template <int N> DEV void cpw() { asm volatile("cp.async.wait_group %0;\n" :: "n"(N)); }

// ---------------- unified pipelined fp16 GEMM ----------------
// A: [M,K] f16, B: [K,N] f16, fp32 accumulate. v = acc + bias.
// MODE 0: Cf = v fp32; if Ab: Ab = relu(bn(v))            [prologue / epilogue]
// MODE 1: Cb = relu(bn(v)) f16                            [ODE GEMM #1 -> h]
// MODE 2: Ab = relu(bn(yin + cnext*v)) f16                [k1 -> midpoint activation]
// MODE 3: t = relu(yin + v);                              [k2 -> block finish]
//         if Cf: Cf = t fp32; if Ab: Ab = relu(bn(t)); if Ch: Ch = t f16
template <int MODE>
__global__ void __launch_bounds__(NTH, 2)
gemm_f16(const f16* __restrict__ A, const f16* __restrict__ B,
         const float* __restrict__ bias,
         const float* __restrict__ mn, const float* __restrict__ iv, const float* __restrict__ bt,
         const float* __restrict__ yin, float cnext,
         float* __restrict__ Cf, f16* __restrict__ Cb, f16* __restrict__ Ab,
         f16* __restrict__ Ch,
         int M, int K, int N)
{
    constexpr int SSET = A_ELE + B_ELE;
    extern __shared__ __align__(16) f16 smem[];

    const int tid = threadIdx.x, lane = tid & 31, warp = tid >> 5;
    const int wm = warp >> 1, wn = warp & 1;
    const int m0 = blockIdx.y * BM, n0 = blockIdx.x * BNT;

    auto stA = [&](int s) -> f16* { return smem + s * SSET; };
    auto stB = [&](int s) -> f16* { return smem + s * SSET + A_ELE; };

    auto load_tile = [&](int s, int kt) {
        const size_t kof = (size_t)kt * BK;
#pragma unroll
        for (int i = 0; i < 4; i++) {              // A: 128 rows x 8 chunks of 16B
            const int ch = tid + i * NTH;
            const int r = ch >> 3, c = (ch & 7) * 8;
            cpa(sptr(stA(s) + r * LDA + c), A + (size_t)(m0 + r) * K + kof + c);
        }
#pragma unroll
        for (int i = 0; i < 4; i++) {              // B: 64 rows x 16 chunks of 16B
            const int ch = tid + i * NTH;
            const int r = ch >> 4, c = (ch & 15) * 8;
            cpa(sptr(stB(s) + r * LDB + c), B + (kof + r) * (size_t)N + n0 + c);
        }
    };

    float acc[2][8][4] = {};

    const int KT = K / BK;
    for (int s = 0; s < S_PIPE - 1; s++) { load_tile(s, s); cpc(); }

    for (int kt = 0; kt < KT; kt++) {
        cpw<S_PIPE - 2>();
        __syncthreads();
        const int nkt = kt + S_PIPE - 1;
        if (nkt < KT) load_tile(nkt % S_PIPE, nkt);
        cpc();

        const int rs = kt % S_PIPE;
        const f16* aS = stA(rs);
        const f16* bS = stB(rs);

        // register double-buffered fragment pipeline
        uint32_t aF[2][2][4], bF[2][8][2];
        auto ldf = [&](int bb, int ks) {
#pragma unroll
            for (int mt = 0; mt < 2; mt++) {
                const int r = wm * 32 + mt * 16 + (lane & 15);
                const int c = ks + ((lane >> 4) << 3);
                ldm4(aF[bb][mt], sptr(aS + r * LDA + c));
            }
#pragma unroll
            for (int np = 0; np < 4; np++) {
                const int r = ks + (((lane >> 3) & 1) << 3) + (lane & 7);
                const int c = wn * 64 + np * 16 + ((lane >> 4) << 3);
                uint32_t t[4];
                ldm4t(t, sptr(bS + r * LDB + c));
                bF[bb][np * 2][0] = t[0]; bF[bb][np * 2][1] = t[1];
                bF[bb][np * 2 + 1][0] = t[2]; bF[bb][np * 2 + 1][1] = t[3];
            }
        };
        ldf(0, 0);
#pragma unroll
        for (int ksi = 0; ksi < BK / 16; ksi++) {
            if (ksi + 1 < BK / 16) ldf((ksi + 1) & 1, (ksi + 1) * 16);
            const int cur = ksi & 1;
#pragma unroll
            for (int mt = 0; mt < 2; mt++)
#pragma unroll
                for (int nt = 0; nt < 8; nt++)
                    mma16816(acc[mt][nt], aF[cur][mt], bF[cur][nt]);
        }
        __syncthreads();
    }

    // ---- epilogue ----
#pragma unroll
    for (int mt = 0; mt < 2; mt++) {
        const int row = m0 + wm * 32 + mt * 16 + (lane >> 2);
#pragma unroll
        for (int nt = 0; nt < 8; nt++) {
            const int col = n0 + wn * 64 + nt * 8 + ((lane & 3) << 1);
            const float2 bs = *reinterpret_cast<const float2*>(bias + col);
            float v0 = acc[mt][nt][0] + bs.x;
            float v1 = acc[mt][nt][1] + bs.y;
            float v2 = acc[mt][nt][2] + bs.x;
            float v3 = acc[mt][nt][3] + bs.y;
            const size_t o0 = (size_t)row * N + col;
            const size_t o1 = (size_t)(row + 8) * N + col;

            if constexpr (MODE == 1) {
                const float2 m2 = *reinterpret_cast<const float2*>(mn + col);
                const float2 i2 = *reinterpret_cast<const float2*>(iv + col);
                const float2 t2 = *reinterpret_cast<const float2*>(bt + col);
                v0 = fmaxf((v0 - m2.x) * i2.x + t2.x, 0.f);
                v1 = fmaxf((v1 - m2.y) * i2.y + t2.y, 0.f);
                v2 = fmaxf((v2 - m2.x) * i2.x + t2.x, 0.f);
                v3 = fmaxf((v3 - m2.y) * i2.y + t2.y, 0.f);
                *reinterpret_cast<uint32_t*>(Cb + o0) = packh(v0, v1);
                *reinterpret_cast<uint32_t*>(Cb + o1) = packh(v2, v3);
            } else if constexpr (MODE == 2) {
                const float2 m2 = *reinterpret_cast<const float2*>(mn + col);
                const float2 i2 = *reinterpret_cast<const float2*>(iv + col);
                const float2 t2 = *reinterpret_cast<const float2*>(bt + col);
                const float2 y0 = *reinterpret_cast<const float2*>(yin + o0);
                const float2 y1 = *reinterpret_cast<const float2*>(yin + o1);
                float a0 = fmaxf((y0.x + cnext * v0 - m2.x) * i2.x + t2.x, 0.f);
                float a1 = fmaxf((y0.y + cnext * v1 - m2.y) * i2.y + t2.y, 0.f);
                float a2 = fmaxf((y1.x + cnext * v2 - m2.x) * i2.x + t2.x, 0.f);
                float a3 = fmaxf((y1.y + cnext * v3 - m2.y) * i2.y + t2.y, 0.f);
                *reinterpret_cast<uint32_t*>(Ab + o0) = packh(a0, a1);
                *reinterpret_cast<uint32_t*>(Ab + o1) = packh(a2, a3);
            } else if constexpr (MODE == 3) {
                const float2 y0 = *reinterpret_cast<const float2*>(yin + o0);
                const float2 y1 = *reinterpret_cast<const float2*>(yin + o1);
                float t0 = fmaxf(y0.x + v0, 0.f);
                float t1 = fmaxf(y0.y + v1, 0.f);
                float t2v = fmaxf(y1.x + v2, 0.f);
                float t3 = fmaxf(y1.y + v3, 0.f);
                if (Cf) {
                    *reinterpret_cast<float2*>(Cf + o0) = make_float2(t0, t1);
                    *reinterpret_cast<float2*>(Cf + o1) = make_float2(t2v, t3);
                }
                if (Ab) {
                    const float2 m2 = *reinterpret_cast<const float2*>(mn + col);
                    const float2 i2 = *reinterpret_cast<const float2*>(iv + col);
                    const float2 b2v = *reinterpret_cast<const float2*>(bt + col);
                    float a0 = fmaxf((t0 - m2.x) * i2.x + b2v.x, 0.f);
                    float a1 = fmaxf((t1 - m2.y) * i2.y + b2v.y, 0.f);
                    float a2 = fmaxf((t2v - m2.x) * i2.x + b2v.x, 0.f);
                    float a3 = fmaxf((t3 - m2.y) * i2.y + b2v.y, 0.f);
                    *reinterpret_cast<uint32_t*>(Ab + o0) = packh(a0, a1);
                    *reinterpret_cast<uint32_t*>(Ab + o1) = packh(a2, a3);
                }
                if (Ch) {
                    *reinterpret_cast<uint32_t*>(Ch + o0) = packh(t0, t1);
                    *reinterpret_cast<uint32_t*>(Ch + o1) = packh(t2v, t3);
                }
            } else {   // MODE 0
                *reinterpret_cast<float2*>(Cf + o0) = make_float2(v0, v1);
                *reinterpret_cast<float2*>(Cf + o1) = make_float2(v2, v3);
                if (Ab) {
                    const float2 m2 = *reinterpret_cast<const float2*>(mn + col);
                    const float2 i2 = *reinterpret_cast<const float2*>(iv + col);
                    const float2 t2 = *reinterpret_cast<const float2*>(bt + col);
                    float a0 = fmaxf((v0 - m2.x) * i2.x + t2.x, 0.f);
                    float a1 = fmaxf((v1 - m2.y) * i2.y + t2.y, 0.f);
                    float a2 = fmaxf((v2 - m2.x) * i2.x + t2.x, 0.f);
                    float a3 = fmaxf((v3 - m2.y) * i2.y + t2.y, 0.f);
                    *reinterpret_cast<uint32_t*>(Ab + o0) = packh(a0, a1);
                    *reinterpret_cast<uint32_t*>(Ab + o1) = packh(a2, a3);
                }
            }
        }
    }
}

// ---------------- prep kernels (2 launches total) ----------------
__global__ void prep_inv(const float* __restrict__ gamma, const float* __restrict__ var,
                         float* __restrict__ inv, int n)
{
    int i = blockIdx.x * blockDim.x + threadIdx.x;
    if (i < n) inv[i] = gamma[i] * rsqrtf(var[i] + BN_EPS);
}

// Batched fp32 -> fp16 conversion over 5 segments (X, W_in, W_out, W1, W2).
constexpr int SEG_X  = BATCH * INDIM / 4;          // 2,097,152
constexpr int SEG_WI = INDIM * HDIM / 4;           //   131,072
constexpr int SEG_WO = HDIM * OUTDIM / 4;          //   131,072
constexpr int SEG_W1 = NBLK * HDIM * HDIM / 4;     //   524,288
constexpr int SEG_W2 = NBLK * HDIM * HDIM / 4;     //   524,288
constexpr int SEG_TOTAL = SEG_X + SEG_WI + SEG_WO + SEG_W1 + SEG_W2;

__global__ void conv_all(const float* __restrict__ X,  f16* __restrict__ xo,
                         const float* __restrict__ Wi, f16* __restrict__ wio,
                         const float* __restrict__ Wo, f16* __restrict__ woo,
                         const float* __restrict__ W1, f16* __restrict__ w1o,
                         const float* __restrict__ W2, f16* __restrict__ w2o)
{
    int i = blockIdx.x * blockDim.x + threadIdx.x;
    if (i >= SEG_TOTAL) return;
    const float* src; f16* dst; int j = i;
    if (j < SEG_X)                  { src = X;  dst = xo; }
    else if ((j -= SEG_X)  < SEG_WI){ src = Wi; dst = wio; }
    else if ((j -= SEG_WI) < SEG_WO){ src = Wo; dst = woo; }
    else if ((j -= SEG_WO) < SEG_W1){ src = W1; dst = w1o; }
    else { j -= SEG_W1;               src = W2; dst = w2o; }
    float4 v = reinterpret_cast<const float4*>(src)[j];
    uint2 o;
    o.x = packh(v.x, v.y);
    o.y = packh(v.z, v.w);
    reinterpret_cast<uint2*>(dst)[j] = o;
}

// ---------------- host ----------------
extern "C" void kernel_launch(void* const* d_in, const int* in_sizes, int n_in,
                              void* d_out, int out_size)
{
    const float* X        = (const float*)d_in[0];
    const float* W_in     = (const float*)d_in[1];
    const float* b_in     = (const float*)d_in[2];
    const float* bn_gamma = (const float*)d_in[3];
    const float* bn_beta  = (const float*)d_in[4];
    const float* bn_mean  = (const float*)d_in[5];
    const float* bn_var   = (const float*)d_in[6];
    const float* W1       = (const float*)d_in[7];
    const float* b1       = (const float*)d_in[8];
    const float* W2       = (const float*)d_in[9];
    const float* b2       = (const float*)d_in[10];
    const float* W_out    = (const float*)d_in[11];
    const float* b_out    = (const float*)d_in[12];

    float *y, *inv;
    f16 *a, *h, *yh, *x, *w1p, *w2p, *wi, *wo;
    cudaGetSymbolAddress((void**)&y,   g_y);
    cudaGetSymbolAddress((void**)&inv, g_inv);
    cudaGetSymbolAddress((void**)&a,   g_a);
    cudaGetSymbolAddress((void**)&h,   g_h);
    cudaGetSymbolAddress((void**)&yh,  g_yh);
    cudaGetSymbolAddress((void**)&x,   g_x);
    cudaGetSymbolAddress((void**)&w1p, g_w1);
    cudaGetSymbolAddress((void**)&w2p, g_w2);
    cudaGetSymbolAddress((void**)&wi,  g_wi);
    cudaGetSymbolAddress((void**)&wo,  g_wo);

    cudaFuncSetAttribute(gemm_f16<0>, cudaFuncAttributeMaxDynamicSharedMemorySize, GEMM_SMEM);
    cudaFuncSetAttribute(gemm_f16<1>, cudaFuncAttributeMaxDynamicSharedMemorySize, GEMM_SMEM);
    cudaFuncSetAttribute(gemm_f16<2>, cudaFuncAttributeMaxDynamicSharedMemorySize, GEMM_SMEM);
    cudaFuncSetAttribute(gemm_f16<3>, cudaFuncAttributeMaxDynamicSharedMemorySize, GEMM_SMEM);

    // ---- prep (2 launches) ----
    prep_inv<<<(NBLK * 2 * HDIM + 255) / 256, 256>>>(bn_gamma, bn_var, inv, NBLK * 2 * HDIM);
    conv_all<<<(SEG_TOTAL + 255) / 256, 256>>>(X, x, W_in, wi, W_out, wo, W1, w1p, W2, w2p);

    const dim3 blk(NTH);
    const dim3 gH(HDIM / BNT, BATCH / BM);     // (8, 128)
    const dim3 gO(OUTDIM / BNT, BATCH / BM);   // (4, 128)

    // ---- prologue: y = X@W_in + b_in; a = relu(bn0_b0(y)) ----
    gemm_f16<0><<<gH, blk, GEMM_SMEM>>>(x, wi, b_in,
                                        bn_mean, inv, bn_beta,
                                        nullptr, 0.f,
                                        y, nullptr, a, nullptr,
                                        BATCH, INDIM, HDIM);

    // ---- RK2 midpoint per block, fully fused:
    //   h    = relu(bn1(a@W1 + b1))                    MODE 1
    //   amid = relu(bn0(y + 0.5*(h@W2+b2)))            MODE 2
    //   h    = relu(bn1(amid@W1 + b1))                 MODE 1
    //   y    = relu(y + (h@W2+b2)); a_next / f16(y)    MODE 3
    for (int b = 0; b < NBLK; ++b) {
        const f16* W1b = w1p + (size_t)b * HDIM * HDIM;
        const f16* W2b = w2p + (size_t)b * HDIM * HDIM;
        const float* b1p = b1 + b * HDIM;
        const float* b2p = b2 + b * HDIM;
        const float* mn0 = bn_mean + (size_t)(b * 2 + 0) * HDIM;
        const float* mn1 = bn_mean + (size_t)(b * 2 + 1) * HDIM;
        const float* bt0 = bn_beta + (size_t)(b * 2 + 0) * HDIM;
        const float* bt1 = bn_beta + (size_t)(b * 2 + 1) * HDIM;
        const float* iv0 = inv + (b * 2 + 0) * HDIM;
        const float* iv1 = inv + (b * 2 + 1) * HDIM;

        gemm_f16<1><<<gH, blk, GEMM_SMEM>>>(a, W1b, b1p,
                                            mn1, iv1, bt1, nullptr, 0.f,
                                            nullptr, h, nullptr, nullptr,
                                            BATCH, HDIM, HDIM);
        gemm_f16<2><<<gH, blk, GEMM_SMEM>>>(h, W2b, b2p,
                                            mn0, iv0, bt0, y, 0.5f,
                                            nullptr, nullptr, a, nullptr,
                                            BATCH, HDIM, HDIM);
        gemm_f16<1><<<gH, blk, GEMM_SMEM>>>(a, W1b, b1p,
                                            mn1, iv1, bt1, nullptr, 0.f,
                                            nullptr, h, nullptr, nullptr,
                                            BATCH, HDIM, HDIM);
        const bool final_blk = (b == NBLK - 1);
        const int nb2 = ((b + 1) * 2) % (NBLK * 2);
        gemm_f16<3><<<gH, blk, GEMM_SMEM>>>(h, W2b, b2p,
                                            bn_mean + (size_t)nb2 * HDIM,
                                            inv + nb2 * HDIM,
                                            bn_beta + (size_t)nb2 * HDIM,
                                            y, 0.f,
                                            final_blk ? nullptr : y,
                                            nullptr,
                                            final_blk ? nullptr : a,
                                            final_blk ? yh : nullptr,
                                            BATCH, HDIM, HDIM);
    }

    // ---- epilogue: out = y @ W_out + b_out ----
    gemm_f16<0><<<gO, blk, GEMM_SMEM>>>(yh, wo, b_out,
                                        nullptr, nullptr, nullptr, nullptr, 0.f,
                                        (float*)d_out, nullptr, nullptr, nullptr,
                                        BATCH, HDIM, OUTDIM);
}